// round 12
// baseline (speedup 1.0000x reference)
#include <cuda_runtime.h>
#include <cstdint>

#define BB 8
#define LL 2048
#define DD 512
#define DM 128
#define HH 1024        // L/2
#define RR 512         // r_actual = L - K
#define NU 512         // H - RR (unmerged kept)
#define LO 1536        // NU + HH

typedef unsigned long long ull;

// ---------------- packed f32x2 helpers ----------------
__device__ __forceinline__ void fma2(ull& d, ull a, ull b, ull c) {
    asm("fma.rn.f32x2 %0, %1, %2, %3;" : "=l"(d) : "l"(a), "l"(b), "l"(c));
}
__device__ __forceinline__ ull dup2(float a) {
    ull r;
    asm("mov.b64 %0, {%1, %1};" : "=l"(r) : "f"(a));
    return r;
}
__device__ __forceinline__ void unpack2(float& lo, float& hi, ull v) {
    asm("mov.b64 {%0, %1}, %2;" : "=f"(lo), "=f"(hi) : "l"(v));
}
// cp.async helpers (LDGSTS)
__device__ __forceinline__ void cp16(uint32_t dst, const void* src) {
    asm volatile("cp.async.cg.shared.global [%0], [%1], 16;" :: "r"(dst), "l"(src));
}
__device__ __forceinline__ void cp_commit() {
    asm volatile("cp.async.commit_group;");
}
__device__ __forceinline__ void cp_wait0() {
    asm volatile("cp.async.wait_group 0;");
}

// ---------------- scratch ----------------
__device__ float g_a[BB * HH * DM];          // normalized metric, even tokens (token-major)
__device__ float g_b[BB * HH * DM];          // normalized metric, odd tokens
__device__ float g_pmax[BB * HH * 2];
__device__ int   g_pidx[BB * HH * 2];
__device__ int   g_unm[BB * NU];
__device__ int   g_cnt[BB * HH];
__device__ int   g_off[BB * HH];
__device__ int   g_csr[BB * RR];

// ---------------- metric = normalize(x @ W)  — double-buffered k-tiles ----------------
#define XST 36
#define WST 132
#define NST 129
#define TILE_F (128 * XST + 32 * WST)   // 8832 floats per buffer
__global__ __launch_bounds__(512) void metric_kernel(const float* __restrict__ x,
                                                     const float* __restrict__ W) {
    extern __shared__ float dynsm[];        // 2*TILE_F floats
    __shared__ float norms[128];

    int tid = threadIdx.x;
    int tx = tid & 31, ty = tid >> 5;
    int rowbase = blockIdx.x * 128;

    const float4* x4 = (const float4*)x;
    const float4* w4 = (const float4*)W;

    int xr[2], xq[2], wk[2], wq[2];
#pragma unroll
    for (int p = 0; p < 2; p++) {
        int idx = p * 512 + tid;
        xr[p] = idx >> 3;  xq[p] = idx & 7;
        wk[p] = idx >> 5;  wq[p] = idx & 31;
    }

    float* buf0 = dynsm;
    float* buf1 = dynsm + TILE_F;

    {
        float* xs = buf0;
        float* ws = buf0 + 128 * XST;
#pragma unroll
        for (int p = 0; p < 2; p++) {
            *(float4*)&xs[xr[p] * XST + xq[p] * 4] =
                x4[(size_t)(rowbase + xr[p]) * (DD / 4) + xq[p]];
            *(float4*)&ws[wk[p] * WST + wq[p] * 4] =
                w4[(size_t)wk[p] * (DM / 4) + wq[p]];
        }
    }
    __syncthreads();

    ull acc2[8][2];
#pragma unroll
    for (int i = 0; i < 8; i++) { acc2[i][0] = 0ull; acc2[i][1] = 0ull; }

    for (int kt = 0; kt < 16; kt++) {
        float* cb = (kt & 1) ? buf1 : buf0;
        float* nb = (kt & 1) ? buf0 : buf1;

        float4 px[2], pw[2];
        if (kt < 15) {
#pragma unroll
            for (int p = 0; p < 2; p++) {
                px[p] = x4[(size_t)(rowbase + xr[p]) * (DD / 4) + (kt + 1) * 8 + xq[p]];
                pw[p] = w4[(size_t)((kt + 1) * 32 + wk[p]) * (DM / 4) + wq[p]];
            }
        }

        float* xs = cb;
        float* ws = cb + 128 * XST;
#pragma unroll
        for (int k4 = 0; k4 < 8; k4++) {
            float4 af[8];
#pragma unroll
            for (int i = 0; i < 8; i++)
                af[i] = *(const float4*)&xs[(ty * 8 + i) * XST + k4 * 4];
#pragma unroll
            for (int kk = 0; kk < 4; kk++) {
                ulonglong2 b2 = *(const ulonglong2*)&ws[(k4 * 4 + kk) * WST + tx * 4];
#pragma unroll
                for (int i = 0; i < 8; i++) {
                    float a = (kk == 0) ? af[i].x : (kk == 1) ? af[i].y : (kk == 2) ? af[i].z : af[i].w;
                    ull a2 = dup2(a);
                    fma2(acc2[i][0], a2, b2.x, acc2[i][0]);
                    fma2(acc2[i][1], a2, b2.y, acc2[i][1]);
                }
            }
        }

        if (kt < 15) {
            float* xd = nb;
            float* wd = nb + 128 * XST;
#pragma unroll
            for (int p = 0; p < 2; p++) {
                *(float4*)&xd[xr[p] * XST + xq[p] * 4] = px[p];
                *(float4*)&wd[wk[p] * WST + wq[p] * 4] = pw[p];
            }
        }
        __syncthreads();
    }

    float acc[8][4];
#pragma unroll
    for (int i = 0; i < 8; i++) {
        unpack2(acc[i][0], acc[i][1], acc2[i][0]);
        unpack2(acc[i][2], acc[i][3], acc2[i][1]);
    }

    float* buf = dynsm;   // [128 rows][NST]
#pragma unroll
    for (int i = 0; i < 8; i++)
#pragma unroll
        for (int c = 0; c < 4; c++)
            buf[(ty * 8 + i) * NST + tx * 4 + c] = acc[i][c];
    __syncthreads();

    if (tid < 128) {
        const float* m = &buf[tid * NST];
        float s[32];
#pragma unroll
        for (int l = 0; l < 32; l++) {
            float t0 = __fmul_rn(m[2 * l],      m[2 * l]);
            float t1 = __fmul_rn(m[2 * l + 1],  m[2 * l + 1]);
            float t2 = __fmul_rn(m[2 * l + 64], m[2 * l + 64]);
            float t3 = __fmul_rn(m[2 * l + 65], m[2 * l + 65]);
            s[l] = __fadd_rn(__fadd_rn(__fadd_rn(t0, t1), t2), t3);
        }
#pragma unroll
        for (int off = 16; off >= 1; off >>= 1)
#pragma unroll
            for (int l = 0; l < 16; l++)
                if (l < off) s[l] = __fadd_rn(s[l], s[l + off]);
        norms[tid] = fmaxf(sqrtf(s[0]), 1e-12f);
    }
    __syncthreads();

#pragma unroll
    for (int i = 0; i < 8; i++) {
        int trow = rowbase + ty * 8 + i;
        int b = trow >> 11;
        int l = trow & (LL - 1);
        float n = norms[ty * 8 + i];
        float* dstbase = ((l & 1) ? g_b : g_a) + ((size_t)b * HH + (l >> 1)) * DM;
        float4 v;
        v.x = __fdiv_rn(acc[i][0], n); v.y = __fdiv_rn(acc[i][1], n);
        v.z = __fdiv_rn(acc[i][2], n); v.w = __fdiv_rn(acc[i][3], n);
        *(float4*)&dstbase[tx * 4] = v;
    }
}

// ---------------- scores = a @ b^T, cp.async-pipelined b-chunks ----------------
#define AST2 132
#define BST2 132
#define STG  132   // staging stride (token-major)
__global__ __launch_bounds__(512) void scores_kernel(const int* __restrict__ mask) {
    extern __shared__ float sm[];
    float* as    = sm;                          // [128][AST2]
    float* bs    = sm + 128 * AST2;             // [128][BST2]  (k-major)
    float* stage = sm + 2 * 128 * AST2;         // [128 tok][STG] raw chunk

    int tid = threadIdx.x;
    int tx = tid & 31, ty = tid >> 5;
    int bb   = blockIdx.x >> 4;
    int tile = (blockIdx.x >> 1) & 7;
    int half = blockIdx.x & 1;
    int rowbase = tile * 128;

    uint32_t stage_u32 = (uint32_t)__cvta_generic_to_shared(stage);

    // per-thread chunk-load coordinates
    int ctok[8], cq[8];
#pragma unroll
    for (int p = 0; p < 8; p++) {
        int idx = p * 512 + tid;
        ctok[p] = idx >> 5; cq[p] = idx & 31;
    }

    // issue cp.async for chunk 0
    {
        const float4* gb = (const float4*)(g_b + ((size_t)bb * HH + (half * 4) * 128) * DM);
#pragma unroll
        for (int p = 0; p < 8; p++)
            cp16(stage_u32 + (uint32_t)(ctok[p] * STG + cq[p] * 4) * 4,
                 &gb[(size_t)ctok[p] * 32 + cq[p]]);
        cp_commit();
    }

    // load a tile [row][k]
    const float4* ga = (const float4*)(g_a + ((size_t)bb * HH + rowbase) * DM);
#pragma unroll
    for (int p = 0; p < 8; p++) {
        int idx = p * 512 + tid;
        int r = idx >> 5, q = idx & 31;
        *(float4*)&as[r * AST2 + q * 4] = ga[(size_t)r * 32 + q];
    }

    float best[8]; int bidx[8];
#pragma unroll
    for (int i = 0; i < 8; i++) { best[i] = -__int_as_float(0x7f800000); bidx[i] = 0; }

    for (int c4 = 0; c4 < 4; c4++) {
        int ch = half * 4 + c4;

        cp_wait0();
        __syncthreads();   // stage ready; all threads done with previous compute

        // transpose stage -> bs (k-major)
#pragma unroll
        for (int p = 0; p < 8; p++) {
            float4 v = *(const float4*)&stage[ctok[p] * STG + cq[p] * 4];
            bs[(cq[p] * 4 + 0) * BST2 + ctok[p]] = v.x;
            bs[(cq[p] * 4 + 1) * BST2 + ctok[p]] = v.y;
            bs[(cq[p] * 4 + 2) * BST2 + ctok[p]] = v.z;
            bs[(cq[p] * 4 + 3) * BST2 + ctok[p]] = v.w;
        }
        __syncthreads();   // bs ready; stage free for next chunk

        if (c4 < 3) {
            const float4* gb = (const float4*)(g_b + ((size_t)bb * HH + (ch + 1) * 128) * DM);
#pragma unroll
            for (int p = 0; p < 8; p++)
                cp16(stage_u32 + (uint32_t)(ctok[p] * STG + cq[p] * 4) * 4,
                     &gb[(size_t)ctok[p] * 32 + cq[p]]);
            cp_commit();
        }

        ull acc2[8][2];
#pragma unroll
        for (int i = 0; i < 8; i++) { acc2[i][0] = 0ull; acc2[i][1] = 0ull; }

#pragma unroll
        for (int k4 = 0; k4 < 32; k4++) {
            float4 af[8];
#pragma unroll
            for (int i = 0; i < 8; i++)
                af[i] = *(const float4*)&as[(ty * 8 + i) * AST2 + k4 * 4];
#pragma unroll
            for (int kk = 0; kk < 4; kk++) {
                ulonglong2 b2 = *(const ulonglong2*)&bs[(k4 * 4 + kk) * BST2 + tx * 4];
#pragma unroll
                for (int i = 0; i < 8; i++) {
                    float a = (kk == 0) ? af[i].x : (kk == 1) ? af[i].y : (kk == 2) ? af[i].z : af[i].w;
                    ull a2 = dup2(a);
                    fma2(acc2[i][0], a2, b2.x, acc2[i][0]);
                    fma2(acc2[i][1], a2, b2.y, acc2[i][1]);
                }
            }
        }

        float acc[8][4];
#pragma unroll
        for (int i = 0; i < 8; i++) {
            unpack2(acc[i][0], acc[i][1], acc2[i][0]);
            unpack2(acc[i][2], acc[i][3], acc2[i][1]);
        }

        bool bm[4];
#pragma unroll
        for (int c = 0; c < 4; c++)
            bm[c] = mask[(size_t)bb * LL + 2 * (ch * 128 + tx * 4 + c) + 1] != 0;

#pragma unroll
        for (int i = 0; i < 8; i++)
#pragma unroll
            for (int c = 0; c < 4; c++) {
                if (bm[c]) {
                    float v = acc[i][c];
                    if (v > best[i]) { best[i] = v; bidx[i] = ch * 128 + tx * 4 + c; }
                }
            }
    }

#pragma unroll
    for (int i = 0; i < 8; i++) {
        if (mask[(size_t)bb * LL + 2 * (rowbase + ty * 8 + i)] == 0) {
            best[i] = -__int_as_float(0x7f800000);
            bidx[i] = 0;
        }
    }

    __syncthreads();
    float* rv = as;
    int*   ri = (int*)bs;
#pragma unroll
    for (int i = 0; i < 8; i++) {
        rv[(ty * 8 + i) * 32 + tx] = best[i];
        ri[(ty * 8 + i) * 32 + tx] = bidx[i];
    }
    __syncthreads();
    if (tid < 128) {
        float bv = rv[tid * 32]; int bi = ri[tid * 32];
        for (int t = 1; t < 32; t++) {
            float v = rv[tid * 32 + t]; int ii = ri[tid * 32 + t];
            if (v > bv || (v == bv && ii < bi)) { bv = v; bi = ii; }
        }
        size_t o = ((size_t)bb * HH + rowbase + tid) * 2 + half;
        g_pmax[o] = bv;
        g_pidx[o] = bi;
    }
}

// ---------------- combine + register bitonic sort + CSR build ----------------
__device__ __forceinline__ ull cmpx(ull a, ull p, bool takeMin) {
    return takeMin ? (a < p ? a : p) : (a > p ? a : p);
}
__global__ __launch_bounds__(512) void sort_kernel() {
    __shared__ ull sk[HH];
    __shared__ int nidx[HH];
    __shared__ int cnt[HH];
    __shared__ int off[HH];
    int b = blockIdx.x, tid = threadIdx.x;
    int e0 = 2 * tid, e1 = 2 * tid + 1;

    ull k0, k1;
#pragma unroll
    for (int c = 0; c < 2; c++) {
        int t = e0 + c;
        size_t o = ((size_t)b * HH + t) * 2;
        float v0 = g_pmax[o], v1 = g_pmax[o + 1];
        int i0 = g_pidx[o], i1 = g_pidx[o + 1];
        float v; int ii;
        if (v1 > v0) { v = v1; ii = i1; } else { v = v0; ii = i0; }
        nidx[t] = ii;
        unsigned u = __float_as_uint(v);
        u = (u & 0x80000000u) ? ~u : (u | 0x80000000u);
        ull key = ((ull)(~u) << 32) | (unsigned)t;
        if (c == 0) k0 = key; else k1 = key;
    }
    __syncthreads();

    for (int k = 2; k <= HH; k <<= 1) {
        bool up = ((e0 & k) == 0);
        for (int j = k >> 1; j >= 64; j >>= 1) {
            sk[e0] = k0; sk[e1] = k1;
            __syncthreads();
            ull p0 = sk[e0 ^ j], p1 = sk[e1 ^ j];
            bool takeMin = (up == ((e0 & j) == 0));
            k0 = cmpx(k0, p0, takeMin);
            k1 = cmpx(k1, p1, takeMin);
            __syncthreads();
        }
        int jstart = ((k >> 1) < 32) ? (k >> 1) : 32;
        for (int j = jstart; j >= 2; j >>= 1) {
            ull p0 = __shfl_xor_sync(0xffffffffu, k0, j >> 1);
            ull p1 = __shfl_xor_sync(0xffffffffu, k1, j >> 1);
            bool takeMin = (up == ((e0 & j) == 0));
            k0 = cmpx(k0, p0, takeMin);
            k1 = cmpx(k1, p1, takeMin);
        }
        {
            ull lo = k0 < k1 ? k0 : k1;
            ull hi = k0 < k1 ? k1 : k0;
            k0 = up ? lo : hi;
            k1 = up ? hi : lo;
        }
    }

    int tok0 = (int)(k0 & 0xFFFFFFFFu);
    int tok1 = (int)(k1 & 0xFFFFFFFFu);
    if (e0 >= RR) g_unm[b * NU + (e0 - RR)] = tok0;
    if (e1 >= RR) g_unm[b * NU + (e1 - RR)] = tok1;

    cnt[e0] = 0; cnt[e1] = 0;
    __syncthreads();
    int d0 = -1, d1 = -1;
    if (e0 < RR) { d0 = nidx[tok0]; atomicAdd(&cnt[d0], 1); }
    if (e1 < RR) { d1 = nidx[tok1]; atomicAdd(&cnt[d1], 1); }
    __syncthreads();
    int* bufA = (int*)sk;
    int* bufB = bufA + HH;
    bufA[e0] = cnt[e0]; bufA[e1] = cnt[e1];
    __syncthreads();
    for (int d = 1; d < HH; d <<= 1) {
        for (int t = tid; t < HH; t += 512)
            bufB[t] = bufA[t] + (t >= d ? bufA[t - d] : 0);
        __syncthreads();
        int* tmp = bufA; bufA = bufB; bufB = tmp;
    }
    for (int t = tid; t < HH; t += 512) {
        int ex = bufA[t] - cnt[t];
        off[t] = ex;
        g_cnt[b * HH + t] = cnt[t];
        g_off[b * HH + t] = ex;
        bufB[t] = 0;
    }
    __syncthreads();
    if (e0 < RR) { int pos = off[d0] + atomicAdd(&bufB[d0], 1); g_csr[b * RR + pos] = tok0; }
    if (e1 < RR) { int pos = off[d1] + atomicAdd(&bufB[d1], 1); g_csr[b * RR + pos] = tok1; }
}

// ---------------- fused assembly: gather + merge-sum + divide + source ones ----------------
__global__ __launch_bounds__(256) void assemble_kernel(const float* __restrict__ x,
                                                       float* __restrict__ out) {
    int w = (blockIdx.x * 256 + threadIdx.x) >> 5;   // 0..12287
    int lane = threadIdx.x & 31;
    int b = w / LO, k = w % LO;
    float* osrc = out + (size_t)BB * LO * DD;

    if (k < NU) {
        int t = g_unm[b * NU + k];
        const float4* src = (const float4*)(x + ((size_t)b * LL + 2 * t) * DD);
        float4* dst = (float4*)(out + ((size_t)b * LO + k) * DD);
#pragma unroll
        for (int p = 0; p < 4; p++) dst[lane + 32 * p] = src[lane + 32 * p];
        if (lane == 0)
            osrc[((size_t)b * LO + k) * LL + 2 * t] = 1.0f;
    } else {
        int j = k - NU;
        const float4* base = (const float4*)(x + ((size_t)b * LL + 2 * j + 1) * DD);
        float4 v[4];
#pragma unroll
        for (int p = 0; p < 4; p++) v[p] = base[lane + 32 * p];
        int c = g_cnt[b * HH + j];
        int o = g_off[b * HH + j];
        for (int i = 0; i < c; i++) {
            int s = g_csr[b * RR + o + i];
            const float4* sr = (const float4*)(x + ((size_t)b * LL + 2 * s) * DD);
#pragma unroll
            for (int p = 0; p < 4; p++) {
                float4 u = sr[lane + 32 * p];
                v[p].x = __fadd_rn(v[p].x, u.x);
                v[p].y = __fadd_rn(v[p].y, u.y);
                v[p].z = __fadd_rn(v[p].z, u.z);
                v[p].w = __fadd_rn(v[p].w, u.w);
            }
        }
        if (c > 0) {
            float den = (float)(c + 1);
#pragma unroll
            for (int p = 0; p < 4; p++) {
                v[p].x = __fdiv_rn(v[p].x, den);
                v[p].y = __fdiv_rn(v[p].y, den);
                v[p].z = __fdiv_rn(v[p].z, den);
                v[p].w = __fdiv_rn(v[p].w, den);
            }
        }
        float4* dst = (float4*)(out + ((size_t)b * LO + k) * DD);
#pragma unroll
        for (int p = 0; p < 4; p++) dst[lane + 32 * p] = v[p];

        float* srow = &osrc[((size_t)b * LO + k) * LL];
        if (lane == 0) srow[2 * j + 1] = 1.0f;
        for (int i = lane; i < c; i += 32)
            srow[2 * g_csr[b * RR + o + i]] = 1.0f;
    }
}

// ---------------- launch ----------------
extern "C" void kernel_launch(void* const* d_in, const int* in_sizes, int n_in,
                              void* d_out, int out_size) {
    const float* x = (const float*)d_in[0];
    const float* W = (const float*)d_in[1];
    const int* mask = (const int*)d_in[2];
    float* out = (float*)d_out;

    (void)in_sizes; (void)n_in; (void)out_size;

    static cudaStream_t s2 = nullptr;
    static cudaEvent_t evFork = nullptr, evJoin = nullptr;
    static bool attrs_set = false;
    if (!s2) {
        cudaStreamCreateWithFlags(&s2, cudaStreamNonBlocking);
        cudaEventCreateWithFlags(&evFork, cudaEventDisableTiming);
        cudaEventCreateWithFlags(&evJoin, cudaEventDisableTiming);
    }
    int metric_smem = 2 * TILE_F * (int)sizeof(float);                          // 70656 B
    int scores_smem = (2 * 128 * AST2 + 128 * STG) * (int)sizeof(float);        // 202752 B
    if (!attrs_set) {
        cudaFuncSetAttribute(metric_kernel, cudaFuncAttributeMaxDynamicSharedMemorySize,
                             metric_smem);
        cudaFuncSetAttribute(scores_kernel, cudaFuncAttributeMaxDynamicSharedMemorySize,
                             scores_smem);
        attrs_set = true;
    }

    // fork: zero the 100MB source region on s2, overlapped with the FMA-bound GEMMs
    cudaEventRecord(evFork, 0);
    cudaStreamWaitEvent(s2, evFork, 0);
    cudaMemsetAsync(out + (size_t)BB * LO * DD, 0,
                    (size_t)BB * LO * LL * sizeof(float), s2);
    cudaEventRecord(evJoin, s2);

    metric_kernel<<<(BB * LL) / 128, 512, metric_smem>>>(x, W);
    scores_kernel<<<BB * 8 * 2, 512, scores_smem>>>(mask);
    sort_kernel<<<BB, 512>>>();

    cudaStreamWaitEvent(0, evJoin, 0);
    assemble_kernel<<<BB * LO / 8, 256>>>(x, out);
}